// round 15
// baseline (speedup 1.0000x reference)
#include <cuda_runtime.h>
#include <cuda_bf16.h>
#include <cuda_fp16.h>
#include <math.h>
#include <stdint.h>

#define NN 50000
#define NE 800000
#define AD 128
#define SD 64
#define NL 4

#define WB 6250           // ceil(NN/8): warp-per-node blocks
#define GCB 782           // ceil(NN/64): 64-row MMA tiles
#define SCB 196           // ceil(NN/256): scan blocks

// ---------------- scratch (static device globals; no allocation) ----------------
__device__ __half d_h2h[NN * AD];              // GCN post-GEMM (dinv-scaled), fp16 for gather
__device__ __half d_th[NN * SD];               // GNA t, fp16 for attention gather
__device__ float d_u[NN * SD];
__device__ float d_proj[NN];
__device__ float d_dinv[NN];
__device__ int   d_deg[NN];
__device__ int   d_off[NN + 1];
__device__ int   d_cur[NN];
__device__ int   d_part[256];
__device__ int   d_csrc[NE];
// bf16 split planes (activations)
__device__ __nv_bfloat16 d_hbf_hi[NN * AD];
__device__ __nv_bfloat16 d_hbf_lo[NN * AD];
__device__ __nv_bfloat16 d_gbf_hi[NN * SD];
__device__ __nv_bfloat16 d_gbf_lo[NN * SD];
// bf16 split planes (weights, transposed K-major: Wt[col][k])
__device__ __nv_bfloat16 d_wthi[NL * AD * AD];
__device__ __nv_bfloat16 d_wtlo[NL * AD * AD];
__device__ __nv_bfloat16 d_w2thi[NL * SD * SD];
__device__ __nv_bfloat16 d_w2tlo[NL * SD * SD];
__device__ __nv_bfloat16 d_w1thi[NL * SD * SD];
__device__ __nv_bfloat16 d_w1tlo[NL * SD * SD];

__device__ __forceinline__ float gelu_exact(float x) {
    return 0.5f * x * (1.0f + erff(x * 0.7071067811865476f));
}
__device__ __forceinline__ uint32_t bfpack(float a, float b) {
    __nv_bfloat162 h = __floats2bfloat162_rn(a, b);
    return *reinterpret_cast<uint32_t*>(&h);
}
__device__ __forceinline__ float bflo(float a) {
    __nv_bfloat16 h = __float2bfloat16(a);
    return a - __bfloat162float(h);
}

// mma.sync m16n8k16 bf16 -> f32 (baseline PTX, sm_80+)
__device__ __forceinline__ void mma_bf16(float* c, const uint32_t* a, const uint32_t* b) {
    asm volatile(
        "mma.sync.aligned.m16n8k16.row.col.f32.bf16.bf16.f32 "
        "{%0,%1,%2,%3}, {%4,%5,%6,%7}, {%8,%9}, {%0,%1,%2,%3};"
        : "+f"(c[0]), "+f"(c[1]), "+f"(c[2]), "+f"(c[3])
        : "r"(a[0]), "r"(a[1]), "r"(a[2]), "r"(a[3]), "r"(b[0]), "r"(b[1]));
}

__device__ __forceinline__ uint32_t smem_to_u32(const void* p) {
    uint32_t a;
    asm("{ .reg .u64 t; cvta.to.shared.u64 t, %1; cvt.u32.u64 %0, t; }" : "=r"(a) : "l"(p));
    return a;
}
// cp.async 16B; pred==0 -> zero-fill (src still a valid clamped address)
__device__ __forceinline__ void cpa16(uint32_t saddr, const void* g, int pred) {
    asm volatile(
        "{\n\t.reg .pred p;\n\tsetp.ne.b32 p, %2, 0;\n\t"
        "@p cp.async.cg.shared.global [%0], [%1], 16;\n\t"
        "@!p cp.async.cg.shared.global [%0], [%1], 16, 0;\n\t}"
        :: "r"(saddr), "l"(g), "r"(pred));
}
#define CP_COMMIT() asm volatile("cp.async.commit_group;" ::: "memory")
#define CP_WAIT(n)  asm volatile("cp.async.wait_group %0;" :: "n"(n) : "memory")

// ---------------- prep: convert x/s/W planes + degree count (grid-fused) ----------------
#define PB_X 3125
#define PB_S 1563
#define PB_D 782
#define PB_WG 32
#define PB_W2 8
#define PB_W1 8
#define PB_TOT (PB_X + PB_S + PB_D + PB_WG + PB_W2 + PB_W1)

__global__ void k_prep(const float* __restrict__ x, const float* __restrict__ s,
                       const int* __restrict__ ei, const float* __restrict__ gcnW,
                       const float* __restrict__ w2W, const float* __restrict__ w1W) {
    int b = blockIdx.x, tid = threadIdx.x;
    if (b < PB_X) {
        int i8 = (b * 256 + tid) * 8;
        float4 f0 = *reinterpret_cast<const float4*>(x + i8);
        float4 f1 = *reinterpret_cast<const float4*>(x + i8 + 4);
        uint4 hv = make_uint4(bfpack(f0.x, f0.y), bfpack(f0.z, f0.w),
                              bfpack(f1.x, f1.y), bfpack(f1.z, f1.w));
        uint4 lv = make_uint4(bfpack(bflo(f0.x), bflo(f0.y)), bfpack(bflo(f0.z), bflo(f0.w)),
                              bfpack(bflo(f1.x), bflo(f1.y)), bfpack(bflo(f1.z), bflo(f1.w)));
        reinterpret_cast<uint4*>(d_hbf_hi)[i8 >> 3] = hv;
        reinterpret_cast<uint4*>(d_hbf_lo)[i8 >> 3] = lv;
    } else if (b < PB_X + PB_S) {
        int i8 = ((b - PB_X) * 256 + tid) * 8;
        if (i8 < NN * SD) {
            float4 f0 = *reinterpret_cast<const float4*>(s + i8);
            float4 f1 = *reinterpret_cast<const float4*>(s + i8 + 4);
            uint4 hv = make_uint4(bfpack(f0.x, f0.y), bfpack(f0.z, f0.w),
                                  bfpack(f1.x, f1.y), bfpack(f1.z, f1.w));
            uint4 lv = make_uint4(bfpack(bflo(f0.x), bflo(f0.y)), bfpack(bflo(f0.z), bflo(f0.w)),
                                  bfpack(bflo(f1.x), bflo(f1.y)), bfpack(bflo(f1.z), bflo(f1.w)));
            reinterpret_cast<uint4*>(d_gbf_hi)[i8 >> 3] = hv;
            reinterpret_cast<uint4*>(d_gbf_lo)[i8 >> 3] = lv;
        }
    } else if (b < PB_X + PB_S + PB_D) {
        int i = (b - PB_X - PB_S) * 256 + tid;
        if (i < NE / 4) {
            int4 d4 = reinterpret_cast<const int4*>(ei + NE)[i];
            atomicAdd(&d_deg[d4.x], 1);
            atomicAdd(&d_deg[d4.y], 1);
            atomicAdd(&d_deg[d4.z], 1);
            atomicAdd(&d_deg[d4.w], 1);
        }
    } else if (b < PB_X + PB_S + PB_D + PB_WG) {
        int base = ((b - PB_X - PB_S - PB_D) * 256 + tid) * 8;
        #pragma unroll
        for (int j = 0; j < 8; j++) {
            int e = base + j;
            int l = e >> 14, r = e & 16383, k = r >> 7, c = r & 127;
            float v = gcnW[e];
            __nv_bfloat16 h = __float2bfloat16(v);
            d_wthi[(l << 14) + c * 128 + k] = h;
            d_wtlo[(l << 14) + c * 128 + k] = __float2bfloat16(v - __bfloat162float(h));
        }
    } else {
        int isW1 = (b >= PB_X + PB_S + PB_D + PB_WG + PB_W2);
        int bb = b - PB_X - PB_S - PB_D - PB_WG - (isW1 ? PB_W2 : 0);
        const float* Wsrc = isW1 ? w1W : w2W;
        __nv_bfloat16* Phi = isW1 ? d_w1thi : d_w2thi;
        __nv_bfloat16* Plo = isW1 ? d_w1tlo : d_w2tlo;
        int base = (bb * 256 + tid) * 8;
        #pragma unroll
        for (int j = 0; j < 8; j++) {
            int e = base + j;
            int l = e >> 12, r = e & 4095, k = r >> 6, c = r & 63;
            float v = Wsrc[e];
            __nv_bfloat16 h = __float2bfloat16(v);
            Phi[(l << 12) + c * 64 + k] = h;
            Plo[(l << 12) + c * 64 + k] = __float2bfloat16(v - __bfloat162float(h));
        }
    }
}

// ---------------- 3-phase scan ----------------
__device__ __forceinline__ int block_incl_scan_256(int v, int* warpsums) {
    int lane = threadIdx.x & 31, wid = threadIdx.x >> 5;
    int x = v;
    #pragma unroll
    for (int o = 1; o < 32; o <<= 1) {
        int y = __shfl_up_sync(0xffffffffu, x, o);
        if (lane >= o) x += y;
    }
    if (lane == 31) warpsums[wid] = x;
    __syncthreads();
    if (wid == 0 && lane < 8) {
        int w = warpsums[lane];
        #pragma unroll
        for (int o = 1; o < 8; o <<= 1) {
            int y = __shfl_up_sync(0xffu, w, o);
            if (lane >= o) w += y;
        }
        warpsums[lane] = w;
    }
    __syncthreads();
    return x + (wid > 0 ? warpsums[wid - 1] : 0);
}

__global__ void k_scanA() {
    __shared__ int ws[8];
    int idx = blockIdx.x * 256 + threadIdx.x;
    int v = (idx < NN) ? d_deg[idx] : 0;
    int incl = block_incl_scan_256(v, ws);
    if (idx < NN) {
        d_off[idx + 1] = incl;                   // local inclusive, fixed up in C
        d_dinv[idx] = rsqrtf((float)(v + 1));
    }
    if (threadIdx.x == 255) d_part[blockIdx.x] = incl;
}

__global__ void k_scanB() {
    __shared__ int ws[8];
    int tid = threadIdx.x;
    int v = (tid < SCB) ? d_part[tid] : 0;
    int incl = block_incl_scan_256(v, ws);
    d_part[tid] = incl - v;                      // exclusive
    if (tid == 0) d_off[0] = 0;
}

__global__ void k_scanC() {
    int idx = blockIdx.x * 256 + threadIdx.x;
    if (idx < NN) {
        int base = d_part[blockIdx.x];
        int incl = d_off[idx + 1] + base;
        d_off[idx + 1] = incl;
        d_cur[idx] = incl - d_deg[idx];
    }
}

__global__ void k_csr_scatter(const int* __restrict__ ei) {
    int i = blockIdx.x * blockDim.x + threadIdx.x;
    if (i < NE / 4) {
        int4 s4 = reinterpret_cast<const int4*>(ei)[i];
        int4 d4 = reinterpret_cast<const int4*>(ei + NE)[i];
        d_csrc[atomicAdd(&d_cur[d4.x], 1)] = s4.x;
        d_csrc[atomicAdd(&d_cur[d4.y], 1)] = s4.y;
        d_csrc[atomicAdd(&d_cur[d4.z], 1)] = s4.z;
        d_csrc[atomicAdd(&d_cur[d4.w], 1)] = s4.w;
    }
}

// ================= fused MMA megakernel: 64-row tiles, 256 thr, 2 blocks/SM =================
#define GC_PITCH 272
#define GC_APLANE 17408          // 64 rows
#define GC_BPLANE 34816          // 128 cols
#define GN_PITCH 144
#define GN_APLANE 9216           // 64 rows
#define GN_BPLANE 18432          // 128 rows ([W2t;W1t])
#define MM_SMEM (2 * GC_APLANE + 2 * GC_BPLANE)   // 104448 -> 2 blocks/SM

__global__ __launch_bounds__(256) void k_mma(
    const __nv_bfloat16* __restrict__ wthi, const __nv_bfloat16* __restrict__ wtlo,
    const __nv_bfloat16* __restrict__ w2thi, const __nv_bfloat16* __restrict__ w2tlo,
    const __nv_bfloat16* __restrict__ w1thi, const __nv_bfloat16* __restrict__ w1tlo,
    const float* __restrict__ b2, const float* __restrict__ b1,
    const float* __restrict__ avec) {
    extern __shared__ char sm[];
    uint32_t sb = smem_to_u32(sm);
    int tid = threadIdx.x;
    int wid = tid >> 5, lane = tid & 31;
    int g = lane >> 2, tg = lane & 3;
    int wm = wid & 1, wn = wid >> 1;       // 2 m-warps x 4 n-warps

    if (blockIdx.x < GCB) {
        // ================== GCN GEMM: 64x128, K=128 ==================
        int r0 = blockIdx.x * 64;
        char* AH = sm;
        char* AL = sm + GC_APLANE;
        char* BH = sm + 2 * GC_APLANE;
        char* BL = sm + 2 * GC_APLANE + GC_BPLANE;
        const uint4* AHg = reinterpret_cast<const uint4*>(d_hbf_hi);
        const uint4* ALg = reinterpret_cast<const uint4*>(d_hbf_lo);
        const uint4* BHg = reinterpret_cast<const uint4*>(wthi);
        const uint4* BLg = reinterpret_cast<const uint4*>(wtlo);
        // group 0: AH + BH
        #pragma unroll
        for (int it = 0; it < 4; it++) {
            int gg = it * 256 + tid;              // 0..1023: A groups
            int row = gg >> 4, c16 = gg & 15;
            int off = row * GC_PITCH + c16 * 16;
            int grow = r0 + row;
            int inb = (grow < NN);
            int cg = inb ? grow : 0;
            cpa16(sb + (uint32_t)(AH - sm) + off, AHg + cg * 16 + c16, inb);
        }
        #pragma unroll
        for (int it = 0; it < 8; it++) {
            int gg = it * 256 + tid;              // 0..2047: B groups
            int row = gg >> 4, c16 = gg & 15;
            int off = row * GC_PITCH + c16 * 16;
            cpa16(sb + (uint32_t)(BH - sm) + off, BHg + gg, 1);
        }
        CP_COMMIT();
        // group 1: AL + BL
        #pragma unroll
        for (int it = 0; it < 4; it++) {
            int gg = it * 256 + tid;
            int row = gg >> 4, c16 = gg & 15;
            int off = row * GC_PITCH + c16 * 16;
            int grow = r0 + row;
            int inb = (grow < NN);
            int cg = inb ? grow : 0;
            cpa16(sb + (uint32_t)(AL - sm) + off, ALg + cg * 16 + c16, inb);
        }
        #pragma unroll
        for (int it = 0; it < 8; it++) {
            int gg = it * 256 + tid;
            int row = gg >> 4, c16 = gg & 15;
            int off = row * GC_PITCH + c16 * 16;
            cpa16(sb + (uint32_t)(BL - sm) + off, BLg + gg, 1);
        }
        CP_COMMIT();
        CP_WAIT(1);
        __syncthreads();

        float acc[2][4][4];
        #pragma unroll
        for (int a = 0; a < 2; a++)
            #pragma unroll
            for (int b = 0; b < 4; b++)
                #pragma unroll
                for (int c = 0; c < 4; c++) acc[a][b][c] = 0.f;

        #pragma unroll
        for (int t = 0; t < 3; t++) {
            if (t == 1) {
                CP_WAIT(0);
                __syncthreads();
            }
            const char* pA = (t == 2) ? AL : AH;
            const char* pB = (t == 1) ? BL : BH;
            #pragma unroll
            for (int k0 = 0; k0 < 8; k0++) {
                int kb = (k0 * 16 + tg * 2) * 2;   // byte col offset
                uint32_t afr[2][4];
                #pragma unroll
                for (int tm = 0; tm < 2; tm++) {
                    int r = wm * 32 + tm * 16 + g;
                    const char* base = pA + r * GC_PITCH + kb;
                    afr[tm][0] = *reinterpret_cast<const uint32_t*>(base);
                    afr[tm][1] = *reinterpret_cast<const uint32_t*>(base + 8 * GC_PITCH);
                    afr[tm][2] = *reinterpret_cast<const uint32_t*>(base + 16);
                    afr[tm][3] = *reinterpret_cast<const uint32_t*>(base + 8 * GC_PITCH + 16);
                }
                uint32_t bfr[4][2];
                #pragma unroll
                for (int tn = 0; tn < 4; tn++) {
                    int n = wn * 32 + tn * 8 + g;
                    const char* base = pB + n * GC_PITCH + kb;
                    bfr[tn][0] = *reinterpret_cast<const uint32_t*>(base);
                    bfr[tn][1] = *reinterpret_cast<const uint32_t*>(base + 16);
                }
                #pragma unroll
                for (int tm = 0; tm < 2; tm++)
                    #pragma unroll
                    for (int tn = 0; tn < 4; tn++)
                        mma_bf16(acc[tm][tn], afr[tm], bfr[tn]);
            }
        }
        // epilogue: scale by dinv[row], store fp16 h2
        #pragma unroll
        for (int tm = 0; tm < 2; tm++) {
            int r1 = r0 + wm * 32 + tm * 16 + g;
            int r2 = r1 + 8;
            float s1 = (r1 < NN) ? d_dinv[r1] : 0.f;
            float s2 = (r2 < NN) ? d_dinv[r2] : 0.f;
            #pragma unroll
            for (int tn = 0; tn < 4; tn++) {
                int c = wn * 32 + tn * 8 + tg * 2;
                if (r1 < NN)
                    *reinterpret_cast<__half2*>(&d_h2h[r1 * AD + c]) =
                        __floats2half2_rn(acc[tm][tn][0] * s1, acc[tm][tn][1] * s1);
                if (r2 < NN)
                    *reinterpret_cast<__half2*>(&d_h2h[r2 * AD + c]) =
                        __floats2half2_rn(acc[tm][tn][2] * s2, acc[tm][tn][3] * s2);
            }
        }
    } else {
        // ================== GNA GEMM: D = A @ [W2t;W1t]^T -> [t | u], K=64 ==================
        int r0 = (blockIdx.x - GCB) * 64;
        char* AH = sm;
        char* AL = sm + GN_APLANE;
        char* BH = sm + 2 * GN_APLANE;
        char* BL = sm + 2 * GN_APLANE + GN_BPLANE;
        const uint4* AHg = reinterpret_cast<const uint4*>(d_gbf_hi);
        const uint4* ALg = reinterpret_cast<const uint4*>(d_gbf_lo);
        const uint4* B2H = reinterpret_cast<const uint4*>(w2thi);
        const uint4* B2L = reinterpret_cast<const uint4*>(w2tlo);
        const uint4* B1H = reinterpret_cast<const uint4*>(w1thi);
        const uint4* B1L = reinterpret_cast<const uint4*>(w1tlo);
        // group 0: AH + BH
        #pragma unroll
        for (int it = 0; it < 2; it++) {
            int gg = it * 256 + tid;              // 0..511: A groups
            int row = gg >> 3, c8 = gg & 7;
            int off = row * GN_PITCH + c8 * 16;
            int grow = r0 + row;
            int inb = (grow < NN);
            int cg = inb ? grow : 0;
            cpa16(sb + (uint32_t)(AH - sm) + off, AHg + cg * 8 + c8, inb);
        }
        #pragma unroll
        for (int it = 0; it < 4; it++) {
            int gg = it * 256 + tid;              // 0..1023: B groups
            int row = gg >> 3, c8 = gg & 7;
            int off = row * GN_PITCH + c8 * 16;
            const uint4* bsrc = (row < 64) ? (B2H + row * 8 + c8) : (B1H + (row - 64) * 8 + c8);
            cpa16(sb + (uint32_t)(BH - sm) + off, bsrc, 1);
        }
        CP_COMMIT();
        // group 1: AL + BL
        #pragma unroll
        for (int it = 0; it < 2; it++) {
            int gg = it * 256 + tid;
            int row = gg >> 3, c8 = gg & 7;
            int off = row * GN_PITCH + c8 * 16;
            int grow = r0 + row;
            int inb = (grow < NN);
            int cg = inb ? grow : 0;
            cpa16(sb + (uint32_t)(AL - sm) + off, ALg + cg * 8 + c8, inb);
        }
        #pragma unroll
        for (int it = 0; it < 4; it++) {
            int gg = it * 256 + tid;
            int row = gg >> 3, c8 = gg & 7;
            int off = row * GN_PITCH + c8 * 16;
            const uint4* bsrc = (row < 64) ? (B2L + row * 8 + c8) : (B1L + (row - 64) * 8 + c8);
            cpa16(sb + (uint32_t)(BL - sm) + off, bsrc, 1);
        }
        CP_COMMIT();
        CP_WAIT(1);
        __syncthreads();

        float acc[2][4][4];
        #pragma unroll
        for (int a = 0; a < 2; a++)
            #pragma unroll
            for (int b = 0; b < 4; b++)
                #pragma unroll
                for (int c = 0; c < 4; c++) acc[a][b][c] = 0.f;

        #pragma unroll
        for (int t = 0; t < 3; t++) {
            if (t == 1) {
                CP_WAIT(0);
                __syncthreads();
            }
            const char* pA = (t == 2) ? AL : AH;
            const char* pB = (t == 1) ? BL : BH;
            #pragma unroll
            for (int k0 = 0; k0 < 4; k0++) {
                int kb = (k0 * 16 + tg * 2) * 2;
                uint32_t afr[2][4];
                #pragma unroll
                for (int tm = 0; tm < 2; tm++) {
                    int r = wm * 32 + tm * 16 + g;
                    const char* base = pA + r * GN_PITCH + kb;
                    afr[tm][0] = *reinterpret_cast<const uint32_t*>(base);
                    afr[tm][1] = *reinterpret_cast<const uint32_t*>(base + 8 * GN_PITCH);
                    afr[tm][2] = *reinterpret_cast<const uint32_t*>(base + 16);
                    afr[tm][3] = *reinterpret_cast<const uint32_t*>(base + 8 * GN_PITCH + 16);
                }
                uint32_t bfr[4][2];
                #pragma unroll
                for (int tn = 0; tn < 4; tn++) {
                    int n = wn * 32 + tn * 8 + g;
                    const char* base = pB + n * GN_PITCH + kb;
                    bfr[tn][0] = *reinterpret_cast<const uint32_t*>(base);
                    bfr[tn][1] = *reinterpret_cast<const uint32_t*>(base + 16);
                }
                #pragma unroll
                for (int tm = 0; tm < 2; tm++)
                    #pragma unroll
                    for (int tn = 0; tn < 4; tn++)
                        mma_bf16(acc[tm][tn], afr[tm], bfr[tn]);
            }
        }
        __syncthreads();   // compute done; smem reusable for proj partials

        float* sP = reinterpret_cast<float*>(sm);   // [64][2]
        int isT = (wn < 2);
        const float* bias = isT ? b2 : b1;
        #pragma unroll
        for (int tm = 0; tm < 2; tm++) {
            int rl1 = wm * 32 + tm * 16 + g;
            int r1 = r0 + rl1;
            int r2 = r1 + 8;
            float p1 = 0.f, p2 = 0.f;
            #pragma unroll
            for (int tn = 0; tn < 4; tn++) {
                int cg = wn * 32 + tn * 8 + tg * 2;       // 0..127 across [t|u]
                int c = isT ? cg : (cg - 64);             // local 0..63
                float2 bb = *reinterpret_cast<const float2*>(&bias[c]);
                float v0 = acc[tm][tn][0] + bb.x;
                float v1 = acc[tm][tn][1] + bb.y;
                float v2 = acc[tm][tn][2] + bb.x;
                float v3 = acc[tm][tn][3] + bb.y;
                if (isT) {
                    float2 av = *reinterpret_cast<const float2*>(&avec[c]);
                    p1 += v0 * av.x + v1 * av.y;
                    p2 += v2 * av.x + v3 * av.y;
                    if (r1 < NN) *reinterpret_cast<__half2*>(&d_th[r1 * SD + c]) = __floats2half2_rn(v0, v1);
                    if (r2 < NN) *reinterpret_cast<__half2*>(&d_th[r2 * SD + c]) = __floats2half2_rn(v2, v3);
                } else {
                    if (r1 < NN) *reinterpret_cast<float2*>(&d_u[r1 * SD + c]) = make_float2(v0, v1);
                    if (r2 < NN) *reinterpret_cast<float2*>(&d_u[r2 * SD + c]) = make_float2(v2, v3);
                }
            }
            if (isT) {
                p1 += __shfl_xor_sync(0xffffffffu, p1, 1);
                p1 += __shfl_xor_sync(0xffffffffu, p1, 2);
                p2 += __shfl_xor_sync(0xffffffffu, p2, 1);
                p2 += __shfl_xor_sync(0xffffffffu, p2, 2);
                if (tg == 0) {
                    sP[rl1 * 2 + wn] = p1;
                    sP[(rl1 + 8) * 2 + wn] = p2;
                }
            }
        }
        __syncthreads();
        if (tid < 64) {
            int row = r0 + tid;
            if (row < NN) d_proj[row] = sP[tid * 2] + sP[tid * 2 + 1];
        }
    }
}

// ================= megakernel B: GCN gather + GNA attn (warp per node), fp16, MLP=8 =================
__global__ void k_mega_edge(const float* __restrict__ bias, float* __restrict__ hout,
                            int fin, float* __restrict__ gout) {
    int tid = threadIdx.x;
    int lane = tid & 31;

    if (blockIdx.x < WB) {
        int n = blockIdx.x * 8 + (tid >> 5);
        if (n >= NN) return;
        int beg = d_off[n], end = d_off[n + 1];
        float din = d_dinv[n];

        const __half2* H2 = reinterpret_cast<const __half2*>(d_h2h);
        int cbase = lane * 2;
        float4 acc, acc2 = make_float4(0.f, 0.f, 0.f, 0.f);
        {
            float2 f0 = __half22float2(H2[n * 64 + cbase]);
            float2 f1 = __half22float2(H2[n * 64 + cbase + 1]);
            acc = make_float4(f0.x, f0.y, f1.x, f1.y);
        }
        int e = beg;
        for (; e + 8 <= end; e += 8) {
            int sx[8];
            #pragma unroll
            for (int q = 0; q < 8; q++) sx[q] = d_csrc[e + q];
            uint2 vv[8];
            #pragma unroll
            for (int q = 0; q < 8; q++)
                vv[q] = *reinterpret_cast<const uint2*>(&H2[sx[q] * 64 + cbase]);
            #pragma unroll
            for (int q = 0; q < 8; q++) {
                float2 a = __half22float2(*reinterpret_cast<__half2*>(&vv[q].x));
                float2 b = __half22float2(*reinterpret_cast<__half2*>(&vv[q].y));
                if (q & 1) {
                    acc2.x += a.x; acc2.y += a.y; acc2.z += b.x; acc2.w += b.y;
                } else {
                    acc.x += a.x; acc.y += a.y; acc.z += b.x; acc.w += b.y;
                }
            }
        }
        for (; e < end; e++) {
            int s0 = d_csrc[e];
            uint2 v0 = *reinterpret_cast<const uint2*>(&H2[s0 * 64 + cbase]);
            float2 a = __half22float2(*reinterpret_cast<__half2*>(&v0.x));
            float2 b = __half22float2(*reinterpret_cast<__half2*>(&v0.y));
            acc.x += a.x; acc.y += a.y; acc.z += b.x; acc.w += b.y;
        }
        acc.x += acc2.x; acc.y += acc2.y; acc.z += acc2.z; acc.w += acc2.w;

        float4 b = *reinterpret_cast<const float4*>(&bias[lane * 4]);
        acc.x = acc.x * din + b.x; acc.y = acc.y * din + b.y;
        acc.z = acc.z * din + b.z; acc.w = acc.w * din + b.w;
        if (!fin) {
            acc.x = gelu_exact(acc.x); acc.y = gelu_exact(acc.y);
            acc.z = gelu_exact(acc.z); acc.w = gelu_exact(acc.w);
            uint2 ph = make_uint2(bfpack(acc.x, acc.y), bfpack(acc.z, acc.w));
            uint2 pl = make_uint2(bfpack(bflo(acc.x), bflo(acc.y)),
                                  bfpack(bflo(acc.z), bflo(acc.w)));
            reinterpret_cast<uint2*>(d_hbf_hi)[n * 32 + lane] = ph;
            reinterpret_cast<uint2*>(d_hbf_lo)[n * 32 + lane] = pl;
        } else {
            *reinterpret_cast<float4*>(&hout[n * AD + lane * 4]) = acc;
        }
    } else {
        int n = (blockIdx.x - WB) * 8 + (tid >> 5);
        if (n >= NN) return;
        int beg = d_off[n], end = d_off[n + 1];
        float projd = d_proj[n];

        float amax = 0.f;
        for (int c = beg; c < end; c += 32) {
            int i = c + lane;
            if (i < end) {
                float a = projd - d_proj[d_csrc[i]];
                amax = fmaxf(amax, a);
            }
        }
        #pragma unroll
        for (int o = 16; o > 0; o >>= 1)
            amax = fmaxf(amax, __shfl_xor_sync(0xffffffffu, amax, o));

        const __half2* TH = reinterpret_cast<const __half2*>(d_th);
        float es = expf(-amax);
        float2 tn = __half22float2(TH[n * 32 + lane]);
        float mx = es * tn.x, my = es * tn.y;
        float den = es;

        for (int c = beg; c < end; c += 32) {
            int i = c + lane;
            int cnt = min(32, end - c);
            int srcl = (i < end) ? d_csrc[i] : 0;
            float al = (i < end) ? (projd - d_proj[srcl]) : 0.f;
            float ewl = expf(al - amax);
            int j = 0;
            for (; j + 8 <= cnt; j += 8) {
                float ee[8];
                int ss[8];
                #pragma unroll
                for (int q = 0; q < 8; q++) {
                    ee[q] = __shfl_sync(0xffffffffu, ewl, j + q);
                    ss[q] = __shfl_sync(0xffffffffu, srcl, j + q);
                }
                float2 tv[8];
                #pragma unroll
                for (int q = 0; q < 8; q++)
                    tv[q] = __half22float2(TH[ss[q] * 32 + lane]);
                #pragma unroll
                for (int q = 0; q < 8; q++) {
                    mx += ee[q] * tv[q].x;
                    my += ee[q] * tv[q].y;
                    den += ee[q];
                }
            }
            for (; j < cnt; j++) {
                float ew = __shfl_sync(0xffffffffu, ewl, j);
                int sj = __shfl_sync(0xffffffffu, srcl, j);
                float2 tv = __half22float2(TH[sj * 32 + lane]);
                mx += ew * tv.x; my += ew * tv.y;
                den += ew;
            }
        }
        float inv = 1.f / (den + 1e-16f);
        float2 uv = *reinterpret_cast<const float2*>(&d_u[n * SD + lane * 2]);
        float2 res;
        res.x = gelu_exact(uv.x + mx * inv);
        res.y = gelu_exact(uv.y + my * inv);
        if (!fin) {
            reinterpret_cast<uint32_t*>(d_gbf_hi)[n * 32 + lane] = bfpack(res.x, res.y);
            reinterpret_cast<uint32_t*>(d_gbf_lo)[n * 32 + lane] = bfpack(bflo(res.x), bflo(res.y));
        } else {
            *reinterpret_cast<float2*>(&gout[n * SD + lane * 2]) = res;
        }
    }
}

// ---------------- host launcher ----------------
extern "C" void kernel_launch(void* const* d_in, const int* in_sizes, int n_in,
                              void* d_out, int out_size) {
    const float* x    = (const float*)d_in[0];
    const float* s    = (const float*)d_in[1];
    const int*   ei   = (const int*)d_in[2];
    const float* gcnW = (const float*)d_in[3];
    const float* gcnb = (const float*)d_in[4];
    const float* w1W  = (const float*)d_in[5];
    const float* w1b  = (const float*)d_in[6];
    const float* w2W  = (const float*)d_in[7];
    const float* w2b  = (const float*)d_in[8];
    const float* ga   = (const float*)d_in[9];
    float* out = (float*)d_out;

    cudaFuncSetAttribute(k_mma, cudaFuncAttributeMaxDynamicSharedMemorySize, MM_SMEM);

    void* p;
    cudaGetSymbolAddress(&p, d_deg);   int* degp = (int*)p;
    cudaGetSymbolAddress(&p, d_wthi);  __nv_bfloat16* wthi = (__nv_bfloat16*)p;
    cudaGetSymbolAddress(&p, d_wtlo);  __nv_bfloat16* wtlo = (__nv_bfloat16*)p;
    cudaGetSymbolAddress(&p, d_w2thi); __nv_bfloat16* w2thi = (__nv_bfloat16*)p;
    cudaGetSymbolAddress(&p, d_w2tlo); __nv_bfloat16* w2tlo = (__nv_bfloat16*)p;
    cudaGetSymbolAddress(&p, d_w1thi); __nv_bfloat16* w1thi = (__nv_bfloat16*)p;
    cudaGetSymbolAddress(&p, d_w1tlo); __nv_bfloat16* w1tlo = (__nv_bfloat16*)p;

    cudaMemsetAsync(degp, 0, NN * sizeof(int));
    k_prep<<<PB_TOT, 256>>>(x, s, ei, gcnW, w2W, w1W);
    k_scanA<<<SCB, 256>>>();
    k_scanB<<<1, 256>>>();
    k_scanC<<<SCB, 256>>>();
    k_csr_scatter<<<(NE / 4 + 255) / 256, 256>>>(ei);

    for (int i = 0; i < NL; i++) {
        k_mma<<<2 * GCB, 256, MM_SMEM>>>(wthi + i * AD * AD, wtlo + i * AD * AD,
                                         w2thi + i * SD * SD, w2tlo + i * SD * SD,
                                         w1thi + i * SD * SD, w1tlo + i * SD * SD,
                                         w2b + i * SD, w1b + i * SD, ga + i * SD);
        k_mega_edge<<<2 * WB, 256>>>(gcnb + i * AD, out, (i == NL - 1) ? 1 : 0, out + NN * AD);
    }
}